// round 7
// baseline (speedup 1.0000x reference)
#include <cuda_runtime.h>
#include <math.h>

#define BB 128
#define JJ 10
#define DD 16
#define II 6400
#define KK 8
#define CC 32
#define REP 200        // capsules per channel
#define GC  32         // one channel per block
#define WS_STRIDE 132  // padded j-row stride for W smem slice

__device__ float g_V[BB * 160];              // V0 (iter-0 outputs)
__device__ float g_part1[BB * GC * 160];     // iter-1 partial s
__device__ float g_part2[BB * GC * 160];     // iter-2 partial s

__device__ __forceinline__ void cp16(float* dst, const float* src) {
    unsigned sdst = (unsigned)__cvta_generic_to_shared(dst);
    asm volatile("cp.async.cg.shared.global [%0], [%1], 16;\n" :: "r"(sdst), "l"(src));
}
__device__ __forceinline__ void cp_commit() { asm volatile("cp.async.commit_group;\n"); }
__device__ __forceinline__ void cp_wait0()  { asm volatile("cp.async.wait_group 0;\n"); }

// ---------------------------------------------------------------------------
// k_sumv0: fused per-channel input sums + iteration-0 output.
// grid BB, block 512.  V0[b] = squash(0.1 * W·Sx[b] + B)
// ---------------------------------------------------------------------------
__global__ __launch_bounds__(512) void k_sumv0(const float* __restrict__ x,
                                               const float* __restrict__ W,
                                               const float* __restrict__ Bv) {
    const int b = blockIdx.x, tid = threadIdx.x;
    __shared__ float Ss[CC * KK];     // Sx[c][k]
    __shared__ float sv[160];
    __shared__ float fb[JJ];

    // thread t: channel c = t/16, slot q = t%16; reads 25 float4 (fixed k-half)
    {
        const int c = tid >> 4, q = tid & 15;
        const float4* xp = reinterpret_cast<const float4*>(x + (size_t)b * II * KK) + c * 400;
        float4 a = make_float4(0.f, 0.f, 0.f, 0.f);
#pragma unroll 5
        for (int r = 0; r < 25; ++r) {
            const float4 v = xp[q + 16 * r];
            a.x += v.x; a.y += v.y; a.z += v.z; a.w += v.w;
        }
#pragma unroll
        for (int m = 2; m <= 8; m <<= 1) {
            a.x += __shfl_xor_sync(0xffffffffu, a.x, m);
            a.y += __shfl_xor_sync(0xffffffffu, a.y, m);
            a.z += __shfl_xor_sync(0xffffffffu, a.z, m);
            a.w += __shfl_xor_sync(0xffffffffu, a.w, m);
        }
        if (q < 2) {   // q==0 -> k 0..3, q==1 -> k 4..7
            Ss[c * KK + q * 4 + 0] = a.x; Ss[c * KK + q * 4 + 1] = a.y;
            Ss[c * KK + q * 4 + 2] = a.z; Ss[c * KK + q * 4 + 3] = a.w;
        }
    }
    __syncthreads();

    if (tid < 160) {
        const int j = tid / DD, d = tid % DD;
        float acc = 0.f;
#pragma unroll 4
        for (int c = 0; c < CC; ++c) {
            const float4 w0 = *reinterpret_cast<const float4*>(
                W + (size_t)(j * CC + c) * 128 + d * 8);
            const float4 w1 = *reinterpret_cast<const float4*>(
                W + (size_t)(j * CC + c) * 128 + d * 8 + 4);
            const float4 s0 = *reinterpret_cast<const float4*>(Ss + c * 8);
            const float4 s1 = *reinterpret_cast<const float4*>(Ss + c * 8 + 4);
            acc = fmaf(w0.x, s0.x, acc); acc = fmaf(w0.y, s0.y, acc);
            acc = fmaf(w0.z, s0.z, acc); acc = fmaf(w0.w, s0.w, acc);
            acc = fmaf(w1.x, s1.x, acc); acc = fmaf(w1.y, s1.y, acc);
            acc = fmaf(w1.z, s1.z, acc); acc = fmaf(w1.w, s1.w, acc);
        }
        sv[tid] = 0.1f * acc + Bv[tid];
    }
    __syncthreads();
    if (tid < JJ) {
        float sq = 0.f;
#pragma unroll
        for (int d = 0; d < DD; ++d) { const float v = sv[tid * DD + d]; sq += v * v; }
        fb[tid] = sqrtf(sq) / (1.0f + sq);
    }
    __syncthreads();
    if (tid < 160) g_V[b * 160 + tid] = sv[tid] * fb[tid / DD];
}

// ---------------------------------------------------------------------------
// k_route: one routing pass, ONE channel per block. grid (GC, BB), block 256.
// ---------------------------------------------------------------------------
__global__ __launch_bounds__(256) void k_route(const float* __restrict__ x,
                                               const float* __restrict__ W,
                                               const float* __restrict__ Bv,
                                               int it) {
    __shared__ float xs[1600];            // [i][k]
    __shared__ float Ws[JJ * WS_STRIDE];  // W[j, c, :, :] padded
    __shared__ float cs[2200];            // [i*11 + j]  (aliased as recon scratch)
    __shared__ float part[960];           // [chunk*20+g][4]
    __shared__ float Tt[80];              // [j*8+k]
    __shared__ float Pq[80];              // [j*8+k]
    __shared__ float Vs[160];

    const int c   = blockIdx.x;
    const int b   = blockIdx.y;
    const int tid = threadIdx.x;
    const float* xb = x + ((size_t)b * II + (size_t)c * REP) * KK;   // 1600 floats

    // async x tile (400 float4)
    for (int t = tid; t < 400; t += 256) cp16(xs + t * 4, xb + t * 4);
    cp_commit();

    // stage W channel slice: 10 rows x 128 floats, padded stride 132
    for (int t = tid; t < 320; t += 256) {
        const int j = t >> 5, f = t & 31;
        *reinterpret_cast<float4*>(Ws + j * WS_STRIDE + f * 4) =
            *reinterpret_cast<const float4*>(W + (size_t)(j * CC + c) * 128 + f * 4);
    }

    // V for this iteration
    if (it == 1) {
        if (tid < 160) Vs[tid] = g_V[b * 160 + tid];
    } else {
        float* red = cs;   // cs unused until phase A
        if (tid < 160) {
            float s = Bv[tid];
#pragma unroll
            for (int g2 = 0; g2 < GC; ++g2)
                s += g_part1[((size_t)b * GC + g2) * 160 + tid];
            red[tid] = s;
        }
        __syncthreads();
        if (tid < JJ) {
            float sq = 0.f;
#pragma unroll
            for (int d = 0; d < DD; ++d) { const float v = red[tid * DD + d]; sq += v * v; }
            red[160 + tid] = sqrtf(sq) / (1.0f + sq);
        }
        __syncthreads();
        if (tid < 160) Vs[tid] = g_V[b * 160 + tid] + red[tid] * red[160 + tid / DD];
    }
    __syncthreads();   // Ws + Vs ready

    // P[j,k] = sum_d Vs[j,d] * Ws[j,d,k]
    if (tid < 80) {
        const int j = tid >> 3, k = tid & 7;
        float acc = 0.f;
#pragma unroll
        for (int d = 0; d < DD; ++d)
            acc = fmaf(Vs[j * DD + d], Ws[j * WS_STRIDE + d * 8 + k], acc);
        Pq[tid] = acc;
    }
    cp_wait0();
    __syncthreads();   // Pq + xs ready

    // ---- phase A: logits + softmax (single pass, thread per capsule) ----
    if (tid < REP) {
        const float4 xa = *reinterpret_cast<const float4*>(xs + tid * 8);
        const float4 xc = *reinterpret_cast<const float4*>(xs + tid * 8 + 4);
        float logit[JJ];
#pragma unroll
        for (int j = 0; j < JJ; ++j) {
            const float4 p0 = *reinterpret_cast<const float4*>(Pq + j * 8);
            const float4 p1 = *reinterpret_cast<const float4*>(Pq + j * 8 + 4);
            float l = 0.f;
            l = fmaf(xa.x, p0.x, l); l = fmaf(xa.y, p0.y, l);
            l = fmaf(xa.z, p0.z, l); l = fmaf(xa.w, p0.w, l);
            l = fmaf(xc.x, p1.x, l); l = fmaf(xc.y, p1.y, l);
            l = fmaf(xc.z, p1.z, l); l = fmaf(xc.w, p1.w, l);
            logit[j] = l;
        }
        float m = logit[0];
#pragma unroll
        for (int j = 1; j < JJ; ++j) m = fmaxf(m, logit[j]);
        float e[JJ], sum = 0.f;
#pragma unroll
        for (int j = 0; j < JJ; ++j) { e[j] = __expf(logit[j] - m); sum += e[j]; }
        const float r = __fdividef(1.0f, sum);
        float* cw = cs + tid * 11;
#pragma unroll
        for (int j = 0; j < JJ; ++j) cw[j] = e[j] * r;
    }
    __syncthreads();

    // ---- phase B: partial T (12 chunks of 17 capsules, 240 threads) ----
    if (tid < 240) {
        const int chunk = tid / 20, g = tid % 20;
        const int j = g >> 1, kh = g & 1;
        const int i0 = chunk * 17;
        const int i1 = (i0 + 17 < REP) ? i0 + 17 : REP;
        float a0 = 0.f, a1 = 0.f, a2 = 0.f, a3 = 0.f;
        const float* xp = xs + i0 * 8 + kh * 4;
        const float* cp = cs + i0 * 11 + j;
#pragma unroll 2
        for (int i = i0; i < i1; ++i) {
            const float4 xv = *reinterpret_cast<const float4*>(xp);
            const float cf = *cp;
            a0 = fmaf(cf, xv.x, a0); a1 = fmaf(cf, xv.y, a1);
            a2 = fmaf(cf, xv.z, a2); a3 = fmaf(cf, xv.w, a3);
            xp += 8; cp += 11;
        }
        *reinterpret_cast<float4*>(part + tid * 4) = make_float4(a0, a1, a2, a3);
    }
    __syncthreads();

    // ---- phase C: combine -> Tt ----
    if (tid < 80) {
        const int j = tid >> 3, k = tid & 7;
        const int g = j * 2 + (k >> 2), q = k & 3;
        float t = 0.f;
#pragma unroll
        for (int chunk = 0; chunk < 12; ++chunk)
            t += part[(chunk * 20 + g) * 4 + q];
        Tt[tid] = t;
    }
    __syncthreads();

    // ---- phase D: partial s -> global ----
    if (tid < 160) {
        const int j = tid / DD, d = tid % DD;
        const float4 w0 = *reinterpret_cast<const float4*>(Ws + j * WS_STRIDE + d * 8);
        const float4 w1 = *reinterpret_cast<const float4*>(Ws + j * WS_STRIDE + d * 8 + 4);
        const float4 t0 = *reinterpret_cast<const float4*>(Tt + j * 8);
        const float4 t1 = *reinterpret_cast<const float4*>(Tt + j * 8 + 4);
        float sreg = 0.f;
        sreg = fmaf(w0.x, t0.x, sreg); sreg = fmaf(w0.y, t0.y, sreg);
        sreg = fmaf(w0.z, t0.z, sreg); sreg = fmaf(w0.w, t0.w, sreg);
        sreg = fmaf(w1.x, t1.x, sreg); sreg = fmaf(w1.y, t1.y, sreg);
        sreg = fmaf(w1.z, t1.z, sreg); sreg = fmaf(w1.w, t1.w, sreg);
        float* dst = (it == 1) ? g_part1 : g_part2;
        dst[((size_t)b * GC + c) * 160 + tid] = sreg;
    }
}

// ---------------------------------------------------------------------------
// k_final: out[b] = squash(sum_c g_part2 + B).  grid BB, block 256.
// ---------------------------------------------------------------------------
__global__ __launch_bounds__(256) void k_final(const float* __restrict__ Bv,
                                               float* __restrict__ out) {
    const int b = blockIdx.x, tid = threadIdx.x;
    __shared__ float sv[160];
    __shared__ float fb[JJ];
    if (tid < 160) {
        float s = Bv[tid];
#pragma unroll
        for (int g2 = 0; g2 < GC; ++g2)
            s += g_part2[((size_t)b * GC + g2) * 160 + tid];
        sv[tid] = s;
    }
    __syncthreads();
    if (tid < JJ) {
        float sq = 0.f;
#pragma unroll
        for (int d = 0; d < DD; ++d) { const float v = sv[tid * DD + d]; sq += v * v; }
        fb[tid] = sqrtf(sq) / (1.0f + sq);
    }
    __syncthreads();
    if (tid < 160) out[(size_t)b * 160 + tid] = sv[tid] * fb[tid / DD];
}

// ---------------------------------------------------------------------------
extern "C" void kernel_launch(void* const* d_in, const int* in_sizes, int n_in,
                              void* d_out, int out_size) {
    const float* x  = (const float*)d_in[0];  // [128, 6400, 8]
    const float* W  = (const float*)d_in[1];  // [10, 32, 16, 8]
    const float* Bv = (const float*)d_in[2];  // [10, 16]
    float* out = (float*)d_out;               // [128, 10, 16]

    k_sumv0<<<BB, 512>>>(x, W, Bv);
    k_route<<<dim3(GC, BB), 256>>>(x, W, Bv, 1);
    k_route<<<dim3(GC, BB), 256>>>(x, W, Bv, 2);
    k_final<<<BB, 256>>>(Bv, out);
}